// round 7
// baseline (speedup 1.0000x reference)
#include <cuda_runtime.h>

// Problem constants (fixed by the dataset; runtime values cross-checked from in_sizes)
#define NN 100000
#define EE 1600000

// ---------------- device scratch (static globals: no allocs allowed) ----------------
__device__ float g_deg_out[NN];
__device__ float g_deg_in[NN];
__device__ float g_onorm[NN];
__device__ float g_inorm[NN];
__device__ float g_h1[NN * 64];
__device__ float g_agg1[NN * 64];
__device__ float g_h2[NN * 40];
__device__ float g_agg2[NN * 40];

// ---------------- small PTX helpers ----------------
__device__ __forceinline__ unsigned long long pack2(float lo, float hi) {
    unsigned long long r;
    asm("mov.b64 %0, {%1, %2};" : "=l"(r) : "f"(lo), "f"(hi));
    return r;
}
__device__ __forceinline__ void unpack2(unsigned long long v, float& lo, float& hi) {
    asm("mov.b64 {%0, %1}, %2;" : "=f"(lo), "=f"(hi) : "l"(v));
}
// packed dual-FMA: d.lo += a.lo*b.lo ; d.hi += a.hi*b.hi  (FFMA2 on sm_103a)
__device__ __forceinline__ void fma2(unsigned long long& d, unsigned long long a,
                                     unsigned long long b) {
    asm("fma.rn.f32x2 %0, %1, %2, %0;" : "+l"(d) : "l"(a), "l"(b));
}
// vectorized no-return reduction (sm_90+): 4 floats per L2 atomic op
__device__ __forceinline__ void red_add_v4(float* addr, float4 v) {
    asm volatile("red.global.add.v4.f32 [%0], {%1, %2, %3, %4};"
                 :: "l"(addr), "f"(v.x), "f"(v.y), "f"(v.z), "f"(v.w)
                 : "memory");
}

// ---------------- kernels ----------------

// Zero all accumulators + degree arrays (output of prior replay must not leak)
__global__ void k_zero() {
    int i = blockIdx.x * blockDim.x + threadIdx.x;
    int stride = gridDim.x * blockDim.x;
    float4 z = make_float4(0.f, 0.f, 0.f, 0.f);
    for (int j = i; j < (NN * 64) / 4; j += stride) ((float4*)g_agg1)[j] = z;
    for (int j = i; j < (NN * 40) / 4; j += stride) ((float4*)g_agg2)[j] = z;
    for (int j = i; j < NN / 4; j += stride) {
        ((float4*)g_deg_out)[j] = z;
        ((float4*)g_deg_in)[j] = z;
    }
}

__global__ void k_degree(const int* __restrict__ src, const int* __restrict__ dst, int e_cnt) {
    int i = blockIdx.x * blockDim.x + threadIdx.x;
    int stride = gridDim.x * blockDim.x;
    for (; i < e_cnt; i += stride) {
        atomicAdd(&g_deg_out[src[i]], 1.0f);  // result unused -> REDG
        atomicAdd(&g_deg_in[dst[i]], 1.0f);
    }
}

__global__ void k_norms(int n) {
    int i = blockIdx.x * blockDim.x + threadIdx.x;
    if (i < n) {
        g_onorm[i] = rsqrtf(fmaxf(g_deg_out[i], 1.0f));
        g_inorm[i] = rsqrtf(fmaxf(g_deg_in[i], 1.0f));
    }
}

// GEMM1: h1[n,64] = (x[n,256] * onorm[n]) @ W1[256,64]
// Block tile 128x64(full N), BK=16, 256 threads, thread tile 8 rows x 4 cols,
// rows paired into f32x2 accumulators (FFMA2).
__global__ __launch_bounds__(256) void k_gemm1(const float* __restrict__ x,
                                               const float* __restrict__ W1, int n) {
    __shared__ float As[16][134];  // [k][m], pad 134 -> conflict-free transpose store + LDS.64 reads
    __shared__ float Bs[16][64];
    __shared__ float Ns[128];

    int tid = threadIdx.x;
    int brow = blockIdx.x * 128;
    int tx = tid & 15;   // col group: cols tx*4 .. tx*4+3
    int ty = tid >> 4;   // row group: rows ty*8 .. ty*8+7

    if (tid < 128) {
        int r = brow + tid;
        Ns[tid] = (r < n) ? g_onorm[r] : 0.f;
    }
    __syncthreads();

    unsigned long long acc[4][4];  // [row-pair][col], each holds (row 2i, row 2i+1)
#pragma unroll
    for (int i = 0; i < 4; i++)
#pragma unroll
        for (int j = 0; j < 4; j++) acc[i][j] = 0ull;

    for (int k0 = 0; k0 < 256; k0 += 16) {
        // load A tile 128x16 (transposed, scaled by out_norm)
#pragma unroll
        for (int t = 0; t < 2; t++) {
            int idx = tid + t * 256;        // 0..511
            int row = idx >> 2;             // 0..127
            int kk = (idx & 3) << 2;        // 0,4,8,12
            int gr = brow + row;
            float4 v = make_float4(0.f, 0.f, 0.f, 0.f);
            if (gr < n) v = *(const float4*)(x + (size_t)gr * 256 + k0 + kk);
            float nm = Ns[row];
            As[kk + 0][row] = v.x * nm;
            As[kk + 1][row] = v.y * nm;
            As[kk + 2][row] = v.z * nm;
            As[kk + 3][row] = v.w * nm;
        }
        // load B tile 16x64
        {
            int kr = tid >> 4;
            int c = (tid & 15) << 2;
            *(float4*)&Bs[kr][c] = *(const float4*)(W1 + (k0 + kr) * 64 + c);
        }
        __syncthreads();

#pragma unroll
        for (int k = 0; k < 16; k++) {
            float4 bq = *(const float4*)&Bs[k][tx << 2];
            unsigned long long b0 = pack2(bq.x, bq.x);
            unsigned long long b1 = pack2(bq.y, bq.y);
            unsigned long long b2 = pack2(bq.z, bq.z);
            unsigned long long b3 = pack2(bq.w, bq.w);
#pragma unroll
            for (int i2 = 0; i2 < 4; i2++) {
                float2 a2 = *(const float2*)&As[k][(ty << 3) + (i2 << 1)];
                unsigned long long ap = pack2(a2.x, a2.y);
                fma2(acc[i2][0], ap, b0);
                fma2(acc[i2][1], ap, b1);
                fma2(acc[i2][2], ap, b2);
                fma2(acc[i2][3], ap, b3);
            }
        }
        __syncthreads();
    }

    // store
#pragma unroll
    for (int i2 = 0; i2 < 4; i2++) {
        int r0 = brow + (ty << 3) + (i2 << 1);
        float lo[4], hi[4];
#pragma unroll
        for (int j = 0; j < 4; j++) unpack2(acc[i2][j], lo[j], hi[j]);
        if (r0 < n)
            *(float4*)(g_h1 + (size_t)r0 * 64 + (tx << 2)) =
                make_float4(lo[0], lo[1], lo[2], lo[3]);
        if (r0 + 1 < n)
            *(float4*)(g_h1 + (size_t)(r0 + 1) * 64 + (tx << 2)) =
                make_float4(hi[0], hi[1], hi[2], hi[3]);
    }
}

// Scatter layer 1: agg1[dst] += h1[src], 64 floats/edge = 16 float4 work items
__global__ void k_scatter64(const int* __restrict__ src, const int* __restrict__ dst,
                            int e_cnt) {
    int i = blockIdx.x * blockDim.x + threadIdx.x;
    int stride = gridDim.x * blockDim.x;
    int total = e_cnt << 4;
    for (; i < total; i += stride) {
        int e = i >> 4;
        int c = (i & 15) << 2;
        int s = src[e];
        int d = dst[e];
        float4 v = *(const float4*)(g_h1 + s * 64 + c);
        red_add_v4(g_agg1 + d * 64 + c, v);
    }
}

// GEMM2 fused with norms:
// h2[n,j] = (in*out)[n] * (agg1[n,:] @ W2)[j] + out[n] * (b1 @ W2)[j]
// Block 128 rows, 128 threads: ct=tid&3 -> cols ct*10..+9, rt=tid>>2 -> rows rt+32*i
__global__ __launch_bounds__(128) void k_gemm2(const float* __restrict__ W2,
                                               const float* __restrict__ b1, int n) {
    __shared__ float As[128][68];  // row-major, pad 68: float4 fill + conflict-free reads
    __shared__ float Ws[64 * 40];
    __shared__ float Bw[40];
    __shared__ float On[128];
    __shared__ float Io[128];

    int tid = threadIdx.x;
    int brow = blockIdx.x * 128;

    for (int i = tid; i < 64 * 40; i += 128) Ws[i] = W2[i];
    if (tid < 40) {
        float s = 0.f;
        for (int k = 0; k < 64; k++) s += b1[k] * W2[k * 40 + tid];
        Bw[tid] = s;
    }
    {
        int r = brow + tid;
        float on = (r < n) ? g_onorm[r] : 0.f;
        float in = (r < n) ? g_inorm[r] : 0.f;
        On[tid] = on;
        Io[tid] = on * in;
    }
    __syncthreads();

    // load A tile 128x64 scaled by in*out
#pragma unroll
    for (int t = 0; t < 16; t++) {
        int idx = tid + t * 128;   // 0..2047
        int row = idx >> 4;        // 0..127
        int c = (idx & 15) << 2;   // 0..60
        int gr = brow + row;
        float4 v = make_float4(0.f, 0.f, 0.f, 0.f);
        if (gr < n) v = *(const float4*)(g_agg1 + (size_t)gr * 64 + c);
        float io = Io[row];
        *(float4*)&As[row][c] = make_float4(v.x * io, v.y * io, v.z * io, v.w * io);
    }
    __syncthreads();

    int ct = tid & 3;
    int rt = tid >> 2;
    int jb = ct * 10;
    float acc[4][10];
#pragma unroll
    for (int i = 0; i < 4; i++)
#pragma unroll
        for (int j = 0; j < 10; j++) acc[i][j] = 0.f;

#pragma unroll 8
    for (int k = 0; k < 64; k++) {
        float w[10];
#pragma unroll
        for (int j = 0; j < 10; j++) w[j] = Ws[k * 40 + jb + j];
#pragma unroll
        for (int i = 0; i < 4; i++) {
            float a = As[rt + 32 * i][k];
#pragma unroll
            for (int j = 0; j < 10; j++) acc[i][j] = fmaf(a, w[j], acc[i][j]);
        }
    }

#pragma unroll
    for (int i = 0; i < 4; i++) {
        int lr = rt + 32 * i;
        int r = brow + lr;
        if (r < n) {
            float on = On[lr];
#pragma unroll
            for (int j = 0; j < 10; j++)
                g_h2[(size_t)r * 40 + jb + j] = acc[i][j] + on * Bw[jb + j];
        }
    }
}

// Scatter layer 2: agg2[dst] += h2[src], 40 floats/edge = 10 float4 work items
__global__ void k_scatter40(const int* __restrict__ src, const int* __restrict__ dst,
                            int e_cnt) {
    int i = blockIdx.x * blockDim.x + threadIdx.x;
    int stride = gridDim.x * blockDim.x;
    int total = e_cnt * 10;
    for (; i < total; i += stride) {
        int e = i / 10;
        int c = (i - e * 10) << 2;
        int s = src[e];
        int d = dst[e];
        float4 v = *(const float4*)(g_h2 + s * 40 + c);
        red_add_v4(g_agg2 + d * 40 + c, v);
    }
}

// out = agg2 * in_norm + b2
__global__ void k_epilogue(const float* __restrict__ b2, float* __restrict__ out, int n) {
    int i = blockIdx.x * blockDim.x + threadIdx.x;
    int total = n * 10;
    if (i >= total) return;
    int r = i / 10;
    int c = (i - r * 10) << 2;
    float in = g_inorm[r];
    float4 v = *(const float4*)(g_agg2 + (size_t)r * 40 + c);
    float4 bb = *(const float4*)(b2 + c);
    *(float4*)(out + (size_t)r * 40 + c) =
        make_float4(fmaf(v.x, in, bb.x), fmaf(v.y, in, bb.y),
                    fmaf(v.z, in, bb.z), fmaf(v.w, in, bb.w));
}

// ---------------- launch ----------------
extern "C" void kernel_launch(void* const* d_in, const int* in_sizes, int n_in,
                              void* d_out, int out_size) {
    const float* x  = (const float*)d_in[0];
    const int* src  = (const int*)d_in[1];
    const int* dst  = (const int*)d_in[2];
    const float* W1 = (const float*)d_in[3];
    const float* b1 = (const float*)d_in[4];
    const float* W2 = (const float*)d_in[5];
    const float* b2 = (const float*)d_in[6];
    float* out = (float*)d_out;

    int n = in_sizes[0] / 256;   // 100000
    int e = in_sizes[1];         // 1600000

    k_zero<<<1184, 256>>>();
    k_degree<<<(e + 255) / 256, 256>>>(src, dst, e);
    k_norms<<<(n + 255) / 256, 256>>>(n);
    k_gemm1<<<(n + 127) / 128, 256>>>(x, W1, n);
    k_scatter64<<<8192, 256>>>(src, dst, e);
    k_gemm2<<<(n + 127) / 128, 128>>>(W2, b1, n);
    k_scatter40<<<8192, 256>>>(src, dst, e);
    k_epilogue<<<(n * 10 + 255) / 256, 256>>>(b2, out, n);
}

// round 10
// speedup vs baseline: 1.1918x; 1.1918x over previous
#include <cuda_runtime.h>

// Problem constants (fixed by the dataset; runtime values cross-checked from in_sizes)
#define NN 100000
#define EE 1600000

// ---------------- device scratch (static globals: no allocs allowed) ----------------
__device__ float g_deg_out[NN];
__device__ float g_deg_in[NN];
__device__ float g_onorm[NN];
__device__ float g_inorm[NN];
__device__ float g_io[NN];          // onorm * inorm
__device__ float g_p[NN * 40];      // (x*onorm) @ W12
__device__ float g_aggP[NN * 40];   // scatter of p
__device__ float g_agg2[NN * 40];   // scatter of h2
__device__ float g_W12[256 * 40];   // W1 @ W2
__device__ float g_c2[40];          // b1 @ W2

// ---------------- small PTX helpers ----------------
__device__ __forceinline__ unsigned long long pack2(float lo, float hi) {
    unsigned long long r;
    asm("mov.b64 %0, {%1, %2};" : "=l"(r) : "f"(lo), "f"(hi));
    return r;
}
__device__ __forceinline__ void unpack2(unsigned long long v, float& lo, float& hi) {
    asm("mov.b64 {%0, %1}, %2;" : "=f"(lo), "=f"(hi) : "l"(v));
}
// packed dual-FMA: d.lo += a.lo*b.lo ; d.hi += a.hi*b.hi  (FFMA2 on sm_103a)
__device__ __forceinline__ void fma2(unsigned long long& d, unsigned long long a,
                                     unsigned long long b) {
    asm("fma.rn.f32x2 %0, %1, %2, %0;" : "+l"(d) : "l"(a), "l"(b));
}
// vectorized no-return reduction (sm_90+): 4 floats per L2 atomic op
__device__ __forceinline__ void red_add_v4(float* addr, float4 v) {
    asm volatile("red.global.add.v4.f32 [%0], {%1, %2, %3, %4};"
                 :: "l"(addr), "f"(v.x), "f"(v.y), "f"(v.z), "f"(v.w)
                 : "memory");
}

// ---------------- kernels ----------------

// Zero accumulators + degree arrays (output of prior replay must not leak)
__global__ void k_zero() {
    int i = blockIdx.x * blockDim.x + threadIdx.x;
    int stride = gridDim.x * blockDim.x;
    float4 z = make_float4(0.f, 0.f, 0.f, 0.f);
    for (int j = i; j < (NN * 40) / 4; j += stride) {
        ((float4*)g_aggP)[j] = z;
        ((float4*)g_agg2)[j] = z;
    }
    for (int j = i; j < NN / 4; j += stride) {
        ((float4*)g_deg_out)[j] = z;
        ((float4*)g_deg_in)[j] = z;
    }
}

__global__ void k_degree(const int* __restrict__ src, const int* __restrict__ dst, int e_cnt) {
    int i = blockIdx.x * blockDim.x + threadIdx.x;
    int stride = gridDim.x * blockDim.x;
    for (; i < e_cnt; i += stride) {
        atomicAdd(&g_deg_out[src[i]], 1.0f);  // result unused -> REDG
        atomicAdd(&g_deg_in[dst[i]], 1.0f);
    }
}

__global__ void k_norms(int n) {
    int i = blockIdx.x * blockDim.x + threadIdx.x;
    if (i < n) {
        float on = rsqrtf(fmaxf(g_deg_out[i], 1.0f));
        float in = rsqrtf(fmaxf(g_deg_in[i], 1.0f));
        g_onorm[i] = on;
        g_inorm[i] = in;
        g_io[i] = on * in;
    }
}

// Precompute W12 = W1 @ W2 (256x40) and c2 = b1 @ W2 (40). W2 cached in smem.
__global__ __launch_bounds__(256) void k_prep(const float* __restrict__ W1,
                                              const float* __restrict__ W2,
                                              const float* __restrict__ b1) {
    __shared__ float Ws[64 * 40];
    int tid = threadIdx.x;
    for (int i = tid; i < 64 * 40; i += 256) Ws[i] = W2[i];
    __syncthreads();
    int gi = blockIdx.x * 256 + tid;
    if (gi < 256 * 40) {
        int r = gi / 40;
        int c = gi - r * 40;
        float s = 0.f;
#pragma unroll 16
        for (int k = 0; k < 64; k++) s = fmaf(W1[r * 64 + k], Ws[k * 40 + c], s);
        g_W12[gi] = s;
    }
    if (gi < 40) {
        float s = 0.f;
#pragma unroll 16
        for (int k = 0; k < 64; k++) s = fmaf(b1[k], Ws[k * 40 + gi], s);
        g_c2[gi] = s;
    }
}

// GEMM: p[n,40] = (x[n,256] * onorm[n]) @ W12[256,40]
// Block tile 256 rows x 40 cols, BK=16, 256 threads.
// tx = tid&7 -> 5 cols, ty = tid>>3 -> 8 rows (4 row-pairs), FFMA2 accumulators.
// B pre-duplicated into f32x2 pairs in smem; A read directly as 8-byte ull -> no packs.
__global__ __launch_bounds__(256) void k_gemmP(const float* __restrict__ x, int n) {
    __shared__ float As[16][258];                 // [k][row], stride 258 -> conflict-free stores
    __shared__ unsigned long long Bsd[16][40];    // dup pairs (w,w)
    __shared__ float Ns[256];

    int tid = threadIdx.x;
    int brow = blockIdx.x * 256;
    int tx = tid & 7;    // cols tx*5 .. tx*5+4
    int ty = tid >> 3;   // rows ty*8 .. ty*8+7

    {
        int r = brow + tid;
        Ns[tid] = (r < n) ? g_onorm[r] : 0.f;
    }
    __syncthreads();

    unsigned long long acc[4][5];
#pragma unroll
    for (int i = 0; i < 4; i++)
#pragma unroll
        for (int j = 0; j < 5; j++) acc[i][j] = 0ull;

    for (int k0 = 0; k0 < 256; k0 += 16) {
        // A tile: 256 rows x 16 k, transposed + scaled (4 float4 loads/thread)
#pragma unroll
        for (int t = 0; t < 4; t++) {
            int idx = tid + t * 256;     // 0..1023
            int row = idx >> 2;          // 0..255
            int kk = (idx & 3) << 2;     // 0,4,8,12
            int gr = brow + row;
            float4 v = make_float4(0.f, 0.f, 0.f, 0.f);
            if (gr < n) v = *(const float4*)(x + (size_t)gr * 256 + k0 + kk);
            float nm = Ns[row];
            As[kk + 0][row] = v.x * nm;
            As[kk + 1][row] = v.y * nm;
            As[kk + 2][row] = v.z * nm;
            As[kk + 3][row] = v.w * nm;
        }
        // B tile 16x40, stored duplicated
#pragma unroll
        for (int t = 0; t < 3; t++) {
            int idx = tid + t * 256;
            if (idx < 640) {
                int kr = idx / 40;
                int c = idx - kr * 40;
                float w = g_W12[(k0 + kr) * 40 + c];
                Bsd[kr][c] = pack2(w, w);
            }
        }
        __syncthreads();

#pragma unroll
        for (int k = 0; k < 16; k++) {
            unsigned long long b[5];
#pragma unroll
            for (int j = 0; j < 5; j++) b[j] = Bsd[k][tx * 5 + j];
#pragma unroll
            for (int i2 = 0; i2 < 4; i2++) {
                unsigned long long ap =
                    *(const unsigned long long*)&As[k][(ty << 3) + (i2 << 1)];
#pragma unroll
                for (int j = 0; j < 5; j++) fma2(acc[i2][j], ap, b[j]);
            }
        }
        __syncthreads();
    }

    // store p
#pragma unroll
    for (int i2 = 0; i2 < 4; i2++) {
        int r0 = brow + (ty << 3) + (i2 << 1);
        float lo[5], hi[5];
#pragma unroll
        for (int j = 0; j < 5; j++) unpack2(acc[i2][j], lo[j], hi[j]);
        if (r0 < n) {
#pragma unroll
            for (int j = 0; j < 5; j++) g_p[(size_t)r0 * 40 + tx * 5 + j] = lo[j];
        }
        if (r0 + 1 < n) {
#pragma unroll
            for (int j = 0; j < 5; j++) g_p[(size_t)(r0 + 1) * 40 + tx * 5 + j] = hi[j];
        }
    }
}

// Scatter 1: aggP[dst] += p[src], 40 floats/edge = 10 float4 work items
__global__ void k_scat1(const int* __restrict__ src, const int* __restrict__ dst,
                        int e_cnt) {
    int i = blockIdx.x * blockDim.x + threadIdx.x;
    int stride = gridDim.x * blockDim.x;
    int total = e_cnt * 10;
    for (; i < total; i += stride) {
        int e = i / 10;
        int c = (i - e * 10) << 2;
        int s = src[e];
        int d = dst[e];
        float4 v = *(const float4*)(g_p + s * 40 + c);
        red_add_v4(g_aggP + d * 40 + c, v);
    }
}

// Scatter 2 with fused h2 recompute:
// h2[s] = io[s]*aggP[s] + onorm[s]*c2 ;  agg2[dst] += h2[src]
__global__ void k_scat2(const int* __restrict__ src, const int* __restrict__ dst,
                        int e_cnt) {
    int i = blockIdx.x * blockDim.x + threadIdx.x;
    int stride = gridDim.x * blockDim.x;
    int total = e_cnt * 10;
    for (; i < total; i += stride) {
        int e = i / 10;
        int c = (i - e * 10) << 2;
        int s = src[e];
        int d = dst[e];
        float io = g_io[s];
        float on = g_onorm[s];
        float4 a = *(const float4*)(g_aggP + s * 40 + c);
        float4 c2 = *(const float4*)(g_c2 + c);
        float4 v = make_float4(fmaf(io, a.x, on * c2.x), fmaf(io, a.y, on * c2.y),
                               fmaf(io, a.z, on * c2.z), fmaf(io, a.w, on * c2.w));
        red_add_v4(g_agg2 + d * 40 + c, v);
    }
}

// out = agg2 * in_norm + b2
__global__ void k_epilogue(const float* __restrict__ b2, float* __restrict__ out, int n) {
    int i = blockIdx.x * blockDim.x + threadIdx.x;
    int total = n * 10;
    if (i >= total) return;
    int r = i / 10;
    int c = (i - r * 10) << 2;
    float in = g_inorm[r];
    float4 v = *(const float4*)(g_agg2 + (size_t)r * 40 + c);
    float4 bb = *(const float4*)(b2 + c);
    *(float4*)(out + (size_t)r * 40 + c) =
        make_float4(fmaf(v.x, in, bb.x), fmaf(v.y, in, bb.y),
                    fmaf(v.z, in, bb.z), fmaf(v.w, in, bb.w));
}

// ---------------- launch ----------------
extern "C" void kernel_launch(void* const* d_in, const int* in_sizes, int n_in,
                              void* d_out, int out_size) {
    const float* x  = (const float*)d_in[0];
    const int* src  = (const int*)d_in[1];
    const int* dst  = (const int*)d_in[2];
    const float* W1 = (const float*)d_in[3];
    const float* b1 = (const float*)d_in[4];
    const float* W2 = (const float*)d_in[5];
    const float* b2 = (const float*)d_in[6];
    float* out = (float*)d_out;

    int n = in_sizes[0] / 256;   // 100000
    int e = in_sizes[1];         // 1600000

    k_zero<<<1184, 256>>>();
    k_degree<<<(e + 255) / 256, 256>>>(src, dst, e);
    k_norms<<<(n + 255) / 256, 256>>>(n);
    k_prep<<<40, 256>>>(W1, W2, b1);
    k_gemmP<<<(n + 255) / 256, 256>>>(x, n);
    k_scat1<<<8192, 256>>>(src, dst, e);
    k_scat2<<<8192, 256>>>(src, dst, e);
    k_epilogue<<<(n * 10 + 255) / 256, 256>>>(b2, out, n);
}

// round 11
// speedup vs baseline: 1.5084x; 1.2657x over previous
#include <cuda_runtime.h>

// Problem constants (fixed by the dataset; runtime values cross-checked from in_sizes)
#define NN 100000
#define EE 1600000

// ---------------- device scratch (static globals: no allocs allowed) ----------------
__device__ float g_deg_out[NN];
__device__ float g_deg_in[NN];
__device__ float g_onorm[NN];
__device__ float g_inorm[NN];
__device__ float g_io[NN];            // onorm * inorm
__device__ float g_p[NN * 40];        // (x*onorm) @ W12
__device__ float g_aggPs[NN * 40];    // io[n] * gather(p)
__device__ float g_W12[256 * 40];     // W1 @ W2
__device__ float g_c2[40];            // b1 @ W2
__device__ int   g_esrc[EE];          // CSR: src ids grouped by dst
__device__ int   g_rowpart[NN];       // per-block exclusive scan partials
__device__ int   g_rowstart[NN];      // CSR row offsets
__device__ int   g_cursor[NN];        // placement cursors
__device__ int   g_bsum[128];
__device__ int   g_bsumoff[128];

// ---------------- small PTX helpers ----------------
__device__ __forceinline__ unsigned long long pack2(float lo, float hi) {
    unsigned long long r;
    asm("mov.b64 %0, {%1, %2};" : "=l"(r) : "f"(lo), "f"(hi));
    return r;
}
__device__ __forceinline__ void unpack2(unsigned long long v, float& lo, float& hi) {
    asm("mov.b64 {%0, %1}, %2;" : "=f"(lo), "=f"(hi) : "l"(v));
}
// packed dual-FMA: d.lo += a.lo*b.lo ; d.hi += a.hi*b.hi  (FFMA2 on sm_103a)
__device__ __forceinline__ void fma2(unsigned long long& d, unsigned long long a,
                                     unsigned long long b) {
    asm("fma.rn.f32x2 %0, %1, %2, %0;" : "+l"(d) : "l"(a), "l"(b));
}

// Block-wide exclusive scan (all threads must participate). nwarps = blockDim/32.
__device__ __forceinline__ int block_exscan(int v, int* total, int nwarps) {
    __shared__ int wsum[32];
    int tid = threadIdx.x, lane = tid & 31, wid = tid >> 5;
    int inc = v;
#pragma unroll
    for (int o = 1; o < 32; o <<= 1) {
        int t = __shfl_up_sync(0xffffffffu, inc, o);
        if (lane >= o) inc += t;
    }
    if (lane == 31) wsum[wid] = inc;
    __syncthreads();
    if (wid == 0) {
        int s = (lane < nwarps) ? wsum[lane] : 0;
#pragma unroll
        for (int o = 1; o < 32; o <<= 1) {
            int t = __shfl_up_sync(0xffffffffu, s, o);
            if (lane >= o) s += t;
        }
        if (lane < nwarps) wsum[lane] = s;
    }
    __syncthreads();
    int base = (wid > 0) ? wsum[wid - 1] : 0;
    *total = wsum[nwarps - 1];
    return base + inc - v;
}

// ---------------- kernels ----------------

// Zero degree counters only (everything else is overwritten each replay)
__global__ void k_zero() {
    int i = blockIdx.x * blockDim.x + threadIdx.x;
    if (i < NN / 4) {
        float4 z = make_float4(0.f, 0.f, 0.f, 0.f);
        ((float4*)g_deg_out)[i] = z;
        ((float4*)g_deg_in)[i] = z;
    }
}

__global__ void k_degree(const int* __restrict__ src, const int* __restrict__ dst, int e_cnt) {
    int i = blockIdx.x * blockDim.x + threadIdx.x;
    if (i < e_cnt) {
        atomicAdd(&g_deg_out[src[i]], 1.0f);  // result unused -> REDG
        atomicAdd(&g_deg_in[dst[i]], 1.0f);
    }
}

// Fused: [blocks 0..nscan) norms + scan phase A (per-block partial scan of in_deg)
//        [blocks nscan..nscan+10) W12 = W1@W2 and c2 = b1@W2
__global__ __launch_bounds__(1024) void k_fusedA(const float* __restrict__ W1,
                                                 const float* __restrict__ W2,
                                                 const float* __restrict__ b1,
                                                 int n, int nscan) {
    int b = blockIdx.x;
    if (b < nscan) {
        int i = b * 1024 + threadIdx.x;
        float din = (i < n) ? g_deg_in[i] : 0.f;
        if (i < n) {
            float dout = g_deg_out[i];
            float on = rsqrtf(fmaxf(dout, 1.0f));
            float inr = rsqrtf(fmaxf(din, 1.0f));
            g_onorm[i] = on;
            g_inorm[i] = inr;
            g_io[i] = on * inr;
        }
        int total;
        int ex = block_exscan((int)din, &total, 32);
        if (i < n) g_rowpart[i] = ex;
        if (threadIdx.x == 0) g_bsum[b] = total;
    } else {
        __shared__ float Ws[64 * 40];
        int tid = threadIdx.x;
        for (int t = tid; t < 64 * 40; t += 1024) Ws[t] = W2[t];
        __syncthreads();
        int gi = (b - nscan) * 1024 + tid;
        if (gi < 256 * 40) {
            int r = gi / 40;
            int c = gi - r * 40;
            float s = 0.f;
#pragma unroll 16
            for (int k = 0; k < 64; k++) s = fmaf(W1[r * 64 + k], Ws[k * 40 + c], s);
            g_W12[gi] = s;
        }
        if (gi < 40) {
            float s = 0.f;
#pragma unroll 16
            for (int k = 0; k < 64; k++) s = fmaf(b1[k], Ws[k * 40 + gi], s);
            g_c2[gi] = s;
        }
    }
}

// Scan phase B: exclusive scan of the block sums (single block)
__global__ void k_scanB(int nb) {
    int tid = threadIdx.x;
    int v = (tid < nb) ? g_bsum[tid] : 0;
    int total;
    int ex = block_exscan(v, &total, 4);
    if (tid < nb) g_bsumoff[tid] = ex;
}

// Scan phase C: final row offsets + cursors
__global__ __launch_bounds__(1024) void k_scanC(int n) {
    int i = blockIdx.x * 1024 + threadIdx.x;
    if (i < n) {
        int rs = g_rowpart[i] + g_bsumoff[blockIdx.x];
        g_rowstart[i] = rs;
        g_cursor[i] = rs;
    }
}

// CSR placement: group src ids by dst
__global__ void k_place(const int* __restrict__ src, const int* __restrict__ dst, int e_cnt) {
    int i = blockIdx.x * blockDim.x + threadIdx.x;
    if (i < e_cnt) {
        int pos = atomicAdd(&g_cursor[dst[i]], 1);
        g_esrc[pos] = src[i];
    }
}

// GEMM: p[n,40] = (x[n,256] * onorm[n]) @ W12[256,40]
// Block tile 256 rows x 40 cols, BK=16, 256 threads, FFMA2 accumulators.
__global__ __launch_bounds__(256) void k_gemmP(const float* __restrict__ x, int n) {
    __shared__ float As[16][258];
    __shared__ unsigned long long Bsd[16][40];
    __shared__ float Ns[256];

    int tid = threadIdx.x;
    int brow = blockIdx.x * 256;
    int tx = tid & 7;    // cols tx*5 .. tx*5+4
    int ty = tid >> 3;   // rows ty*8 .. ty*8+7

    {
        int r = brow + tid;
        Ns[tid] = (r < n) ? g_onorm[r] : 0.f;
    }
    __syncthreads();

    unsigned long long acc[4][5];
#pragma unroll
    for (int i = 0; i < 4; i++)
#pragma unroll
        for (int j = 0; j < 5; j++) acc[i][j] = 0ull;

    for (int k0 = 0; k0 < 256; k0 += 16) {
#pragma unroll
        for (int t = 0; t < 4; t++) {
            int idx = tid + t * 256;
            int row = idx >> 2;
            int kk = (idx & 3) << 2;
            int gr = brow + row;
            float4 v = make_float4(0.f, 0.f, 0.f, 0.f);
            if (gr < n) v = *(const float4*)(x + (size_t)gr * 256 + k0 + kk);
            float nm = Ns[row];
            As[kk + 0][row] = v.x * nm;
            As[kk + 1][row] = v.y * nm;
            As[kk + 2][row] = v.z * nm;
            As[kk + 3][row] = v.w * nm;
        }
#pragma unroll
        for (int t = 0; t < 3; t++) {
            int idx = tid + t * 256;
            if (idx < 640) {
                int kr = idx / 40;
                int c = idx - kr * 40;
                float w = g_W12[(k0 + kr) * 40 + c];
                Bsd[kr][c] = pack2(w, w);
            }
        }
        __syncthreads();

#pragma unroll
        for (int k = 0; k < 16; k++) {
            unsigned long long b[5];
#pragma unroll
            for (int j = 0; j < 5; j++) b[j] = Bsd[k][tx * 5 + j];
#pragma unroll
            for (int i2 = 0; i2 < 4; i2++) {
                unsigned long long ap =
                    *(const unsigned long long*)&As[k][(ty << 3) + (i2 << 1)];
#pragma unroll
                for (int j = 0; j < 5; j++) fma2(acc[i2][j], ap, b[j]);
            }
        }
        __syncthreads();
    }

#pragma unroll
    for (int i2 = 0; i2 < 4; i2++) {
        int r0 = brow + (ty << 3) + (i2 << 1);
        float lo[5], hi[5];
#pragma unroll
        for (int j = 0; j < 5; j++) unpack2(acc[i2][j], lo[j], hi[j]);
        if (r0 < n) {
#pragma unroll
            for (int j = 0; j < 5; j++) g_p[(size_t)r0 * 40 + tx * 5 + j] = lo[j];
        }
        if (r0 + 1 < n) {
#pragma unroll
            for (int j = 0; j < 5; j++) g_p[(size_t)(r0 + 1) * 40 + tx * 5 + j] = hi[j];
        }
    }
}

// Gather 1: aggPs[node] = io[node] * sum_{e: dst=node} p[src_e]
// Thread = (node, float4-chunk). 10 consecutive threads cover one node's 160B row.
__global__ void k_gather1(int n) {
    int i = blockIdx.x * blockDim.x + threadIdx.x;
    if (i >= n * 10) return;
    int node = i / 10;
    int c = (i - node * 10) << 2;
    int start = g_rowstart[node];
    int deg = (int)g_deg_in[node];
    const int* ep = g_esrc + start;
    float4 acc = make_float4(0.f, 0.f, 0.f, 0.f);
    int j = 0;
    for (; j + 4 <= deg; j += 4) {
        int s0 = ep[j], s1 = ep[j + 1], s2 = ep[j + 2], s3 = ep[j + 3];
        float4 v0 = *(const float4*)(g_p + s0 * 40 + c);
        float4 v1 = *(const float4*)(g_p + s1 * 40 + c);
        float4 v2 = *(const float4*)(g_p + s2 * 40 + c);
        float4 v3 = *(const float4*)(g_p + s3 * 40 + c);
        acc.x += v0.x; acc.y += v0.y; acc.z += v0.z; acc.w += v0.w;
        acc.x += v1.x; acc.y += v1.y; acc.z += v1.z; acc.w += v1.w;
        acc.x += v2.x; acc.y += v2.y; acc.z += v2.z; acc.w += v2.w;
        acc.x += v3.x; acc.y += v3.y; acc.z += v3.z; acc.w += v3.w;
    }
    for (; j < deg; j++) {
        int s = ep[j];
        float4 v = *(const float4*)(g_p + s * 40 + c);
        acc.x += v.x; acc.y += v.y; acc.z += v.z; acc.w += v.w;
    }
    float io = g_io[node];
    *(float4*)(g_aggPs + (size_t)node * 40 + c) =
        make_float4(acc.x * io, acc.y * io, acc.z * io, acc.w * io);
}

// Gather 2 + epilogue:
// out[d] = inorm[d] * ( sum aggPs[src] + c2 * sum onorm[src] ) + b2
__global__ void k_gather2(const float* __restrict__ b2, float* __restrict__ out, int n) {
    int i = blockIdx.x * blockDim.x + threadIdx.x;
    if (i >= n * 10) return;
    int node = i / 10;
    int c = (i - node * 10) << 2;
    int start = g_rowstart[node];
    int deg = (int)g_deg_in[node];
    const int* ep = g_esrc + start;
    float4 acc = make_float4(0.f, 0.f, 0.f, 0.f);
    float son = 0.f;
    int j = 0;
    for (; j + 2 <= deg; j += 2) {
        int s0 = ep[j], s1 = ep[j + 1];
        float4 v0 = *(const float4*)(g_aggPs + (size_t)s0 * 40 + c);
        float4 v1 = *(const float4*)(g_aggPs + (size_t)s1 * 40 + c);
        float o0 = g_onorm[s0], o1 = g_onorm[s1];
        acc.x += v0.x; acc.y += v0.y; acc.z += v0.z; acc.w += v0.w;
        acc.x += v1.x; acc.y += v1.y; acc.z += v1.z; acc.w += v1.w;
        son += o0; son += o1;
    }
    for (; j < deg; j++) {
        int s = ep[j];
        float4 v = *(const float4*)(g_aggPs + (size_t)s * 40 + c);
        acc.x += v.x; acc.y += v.y; acc.z += v.z; acc.w += v.w;
        son += g_onorm[s];
    }
    float4 c2 = *(const float4*)(g_c2 + c);
    float4 bb = *(const float4*)(b2 + c);
    float inr = g_inorm[node];
    *(float4*)(out + (size_t)node * 40 + c) =
        make_float4(fmaf(inr, fmaf(c2.x, son, acc.x), bb.x),
                    fmaf(inr, fmaf(c2.y, son, acc.y), bb.y),
                    fmaf(inr, fmaf(c2.z, son, acc.z), bb.z),
                    fmaf(inr, fmaf(c2.w, son, acc.w), bb.w));
}

// ---------------- launch ----------------
extern "C" void kernel_launch(void* const* d_in, const int* in_sizes, int n_in,
                              void* d_out, int out_size) {
    const float* x  = (const float*)d_in[0];
    const int* src  = (const int*)d_in[1];
    const int* dst  = (const int*)d_in[2];
    const float* W1 = (const float*)d_in[3];
    const float* b1 = (const float*)d_in[4];
    const float* W2 = (const float*)d_in[5];
    const float* b2 = (const float*)d_in[6];
    float* out = (float*)d_out;

    int n = in_sizes[0] / 256;   // 100000
    int e = in_sizes[1];         // 1600000

    int nscan = (n + 1023) / 1024;         // 98
    int nprep = (256 * 40 + 1023) / 1024;  // 10

    k_zero<<<(NN / 4 + 255) / 256, 256>>>();
    k_degree<<<(e + 255) / 256, 256>>>(src, dst, e);
    k_fusedA<<<nscan + nprep, 1024>>>(W1, W2, b1, n, nscan);
    k_scanB<<<1, 128>>>(nscan);
    k_scanC<<<nscan, 1024>>>(n);
    k_place<<<(e + 255) / 256, 256>>>(src, dst, e);
    k_gemmP<<<(n + 255) / 256, 256>>>(x, n);
    k_gather1<<<(n * 10 + 255) / 256, 256>>>(n);
    k_gather2<<<(n * 10 + 255) / 256, 256>>>(b2, out, n);
}